// round 1
// baseline (speedup 1.0000x reference)
#include <cuda_runtime.h>
#include <cstdint>
#include <math.h>

typedef unsigned long long ull;

__device__ __forceinline__ ull pack2(float lo, float hi) {
    ull r; asm("mov.b64 %0, {%1, %2};" : "=l"(r) : "f"(lo), "f"(hi)); return r;
}
__device__ __forceinline__ void unpack2(ull v, float& lo, float& hi) {
    asm("mov.b64 {%0, %1}, %2;" : "=f"(lo), "=f"(hi) : "l"(v));
}
__device__ __forceinline__ ull ffma2(ull a, ull b, ull c) {
    ull d; asm("fma.rn.f32x2 %0, %1, %2, %3;" : "=l"(d) : "l"(a), "l"(b), "l"(c)); return d;
}

static constexpr int B = 8, C = 128, T = 128, F = 512, K = 64;
static constexpr int FC = 128;     // F columns per CTA in main kernel
static constexpr int PXF = 132;    // pitch (floats) for 128-wide smem tiles (16B-aligned rows)
static constexpr int PXK = 68;     // pitch (floats) for 64-wide smem tiles

// scratch for k/v projections of the latent path: [b*T+t][c][k]
__device__ float g_kbuf[(size_t)B * T * C * K];
__device__ float g_vbuf[(size_t)B * T * C * K];

// ---------------------------------------------------------------------------
// Core SIMT GEMM: out[r][f] = sum_c W[r][c] * Xin[c][f], 256 threads.
// r = ty + 16*i (i < RT), f = 2*(tx + 16*jp) + {0,1} (jp < NP).
// Weights streamed from global in 16-column chunks through smem Wts[R][16].
// Accumulators are packed f32x2.
// ---------------------------------------------------------------------------
template <int RT, int NP, int PX>
__device__ __forceinline__ void gemm_core(
    const float* __restrict__ Wglob,   // [RT*16][128] row-major
    const float* __restrict__ Xin,     // smem tile, pitch PX
    float* __restrict__ Wts,           // smem staging [RT*16][16]
    ull acc[RT][NP], int tid)
{
    const int tx = tid & 15, ty = tid >> 4;
    constexpr int R = RT * 16;
    for (int c0 = 0; c0 < 128; c0 += 16) {
        __syncthreads();   // prior consumers of Wts done; prior smem writes visible
        #pragma unroll
        for (int idx = tid; idx < R * 4; idx += 256) {
            int r = idx >> 2, q = idx & 3;
            float4 v = *reinterpret_cast<const float4*>(Wglob + r * 128 + c0 + q * 4);
            *reinterpret_cast<float4*>(Wts + r * 16 + q * 4) = v;
        }
        __syncthreads();
        #pragma unroll 2
        for (int cc = 0; cc < 16; ++cc) {
            const float* xrow = Xin + (c0 + cc) * PX;
            ull xp[NP];
            #pragma unroll
            for (int jp = 0; jp < NP; ++jp)
                xp[jp] = *reinterpret_cast<const ull*>(xrow + 2 * (tx + 16 * jp));
            #pragma unroll
            for (int i = 0; i < RT; ++i) {
                float w = Wts[(ty + 16 * i) * 16 + cc];
                ull wp = pack2(w, w);
                #pragma unroll
                for (int jp = 0; jp < NP; ++jp)
                    acc[i][jp] = ffma2(wp, xp[jp], acc[i][jp]);
            }
        }
    }
}

__device__ __forceinline__ float silu_f(float g) {
    return g / (1.0f + expf(-g));
}

// ---------------------------------------------------------------------------
// Kernel 1: latent path. One CTA per (b,t) frame.
// latent[b,:,t,:] (128x64) -> rmsnorm -> silu(lp_w@.) -> k/v proj -> scratch.
// ---------------------------------------------------------------------------
static constexpr int K1_XL = 0;
static constexpr int K1_LH = 128 * PXK;
static constexpr int K1_WT = K1_LH + 128 * PXK;
static constexpr int K1_RS = K1_WT + 128 * 16;
static constexpr int K1_SMEM_BYTES = (K1_RS + 64) * 4;

__global__ void __launch_bounds__(256, 1) latent_kernel(
    const float* __restrict__ latent, const float* __restrict__ lp_gamma,
    const float* __restrict__ lp_w,   const float* __restrict__ lp_b,
    const float* __restrict__ k_w,    const float* __restrict__ k_b,
    const float* __restrict__ v_w,    const float* __restrict__ v_b)
{
    extern __shared__ float sm[];
    float* Xl  = sm + K1_XL;
    float* Lh  = sm + K1_LH;
    float* Wts = sm + K1_WT;
    float* rstd = sm + K1_RS;
    const int tid = threadIdx.x;
    const int frame = blockIdx.x;            // b*T + t
    const int b = frame / T, t = frame % T;
    const int tx = tid & 15, ty = tid >> 4;

    // load latent frame [128][64]
    const float* src = latent + ((size_t)b * C * T + t) * K;
    #pragma unroll
    for (int idx = tid; idx < 128 * 16; idx += 256) {
        int r = idx >> 4, q = idx & 15;
        float4 v = *reinterpret_cast<const float4*>(src + (size_t)r * (T * K) + q * 4);
        *reinterpret_cast<float4*>(Xl + r * PXK + q * 4) = v;
    }
    __syncthreads();
    if (tid < 64) {
        float s0 = 0, s1 = 0, s2 = 0, s3 = 0;
        for (int c = 0; c < 128; c += 4) {
            float a = Xl[c * PXK + tid], bb = Xl[(c + 1) * PXK + tid];
            float cc = Xl[(c + 2) * PXK + tid], dd = Xl[(c + 3) * PXK + tid];
            s0 += a * a; s1 += bb * bb; s2 += cc * cc; s3 += dd * dd;
        }
        rstd[tid] = rsqrtf((s0 + s1 + s2 + s3) * (1.0f / 128.0f) + 1e-6f);
    }
    __syncthreads();
    #pragma unroll
    for (int idx = tid; idx < 128 * 16; idx += 256) {
        int r = idx >> 4, q = idx & 15;
        float g = lp_gamma[r];
        float* d = Xl + r * PXK + q * 4;
        d[0] *= rstd[q * 4 + 0] * g; d[1] *= rstd[q * 4 + 1] * g;
        d[2] *= rstd[q * 4 + 2] * g; d[3] *= rstd[q * 4 + 3] * g;
    }
    // no explicit sync needed: gemm_core begins with __syncthreads()

    // latent_h = silu(lp_w @ Xn + lp_b)
    {
        ull acc[8][2] = {};
        gemm_core<8, 2, PXK>(lp_w, Xl, Wts, acc, tid);
        #pragma unroll
        for (int i = 0; i < 8; ++i) {
            int r = ty + 16 * i;
            float bias = lp_b[r];
            #pragma unroll
            for (int jp = 0; jp < 2; ++jp) {
                float lo, hi; unpack2(acc[i][jp], lo, hi);
                lo += bias; hi += bias;
                lo = silu_f(lo); hi = silu_f(hi);
                int fl = 2 * (tx + 16 * jp);
                Lh[r * PXK + fl] = lo; Lh[r * PXK + fl + 1] = hi;
            }
        }
    }
    // k projection -> g_kbuf
    {
        ull acc[8][2] = {};
        gemm_core<8, 2, PXK>(k_w, Lh, Wts, acc, tid);
        float* dst = g_kbuf + (size_t)frame * (C * K);
        #pragma unroll
        for (int i = 0; i < 8; ++i) {
            int r = ty + 16 * i;
            float bias = k_b[r];
            #pragma unroll
            for (int jp = 0; jp < 2; ++jp) {
                float lo, hi; unpack2(acc[i][jp], lo, hi);
                int fl = 2 * (tx + 16 * jp);
                float2 st = make_float2(lo + bias, hi + bias);
                *reinterpret_cast<float2*>(dst + r * K + fl) = st;
            }
        }
    }
    // v projection -> g_vbuf
    {
        ull acc[8][2] = {};
        gemm_core<8, 2, PXK>(v_w, Lh, Wts, acc, tid);
        float* dst = g_vbuf + (size_t)frame * (C * K);
        #pragma unroll
        for (int i = 0; i < 8; ++i) {
            int r = ty + 16 * i;
            float bias = v_b[r];
            #pragma unroll
            for (int jp = 0; jp < 2; ++jp) {
                float lo, hi; unpack2(acc[i][jp], lo, hi);
                int fl = 2 * (tx + 16 * jp);
                float2 st = make_float2(lo + bias, hi + bias);
                *reinterpret_cast<float2*>(dst + r * K + fl) = st;
            }
        }
    }
}

// ---------------------------------------------------------------------------
// Kernel 2: fused side path + attention + FFN. One CTA per (b, t, f-chunk).
// smem: Xs/Hs 128x132, Ks/Vs 128x68, Wts 256x16, rstd 128.
// ---------------------------------------------------------------------------
static constexpr int K2_XS = 0;
static constexpr int K2_HS = 128 * PXF;                 // 16896
static constexpr int K2_KS = K2_HS + 128 * PXF;         // 33792
static constexpr int K2_VS = K2_KS + 128 * PXK;         // 42496
static constexpr int K2_WT = K2_VS + 128 * PXK;         // 51200
static constexpr int K2_RS = K2_WT + 256 * 16;          // 55296
static constexpr int K2_SMEM_BYTES = (K2_RS + 128) * 4; // 221,696 B

__global__ void __launch_bounds__(256, 1) main_kernel(
    const float* __restrict__ side,      const float* __restrict__ basis,
    const float* __restrict__ qn_gamma,
    const float* __restrict__ qmlp_in_w, const float* __restrict__ qmlp_in_b,
    const float* __restrict__ qmlp_out_w,const float* __restrict__ qmlp_out_b,
    const float* __restrict__ q_w,       const float* __restrict__ q_b,
    const float* __restrict__ o_w,       const float* __restrict__ o_b,
    const float* __restrict__ ffn_gamma,
    const float* __restrict__ ffn_in_w,  const float* __restrict__ ffn_in_b,
    const float* __restrict__ ffn_out_w, const float* __restrict__ ffn_out_b,
    const float* __restrict__ score_scale, const float* __restrict__ prior_scale,
    const float* __restrict__ query_skip_scale,
    float* __restrict__ out)
{
    extern __shared__ float sm[];
    float* Xs  = sm + K2_XS;
    float* Hs  = sm + K2_HS;
    float* Ks  = sm + K2_KS;
    float* Vs  = sm + K2_VS;
    float* Wts = sm + K2_WT;
    float* rstd = sm + K2_RS;

    const int tid = threadIdx.x;
    const int fc = blockIdx.x;      // 0..3
    const int t  = blockIdx.y;
    const int b  = blockIdx.z;
    const int f0 = fc * FC;
    const int tx = tid & 15, ty = tid >> 4;
    const int frame = b * T + t;

    // ---- load k/v frame into smem ----
    {
        const float* ksrc = g_kbuf + (size_t)frame * (C * K);
        const float* vsrc = g_vbuf + (size_t)frame * (C * K);
        #pragma unroll
        for (int idx = tid; idx < 128 * 16; idx += 256) {
            int r = idx >> 4, q = idx & 15;
            float4 kv = *reinterpret_cast<const float4*>(ksrc + r * K + q * 4);
            float4 vv = *reinterpret_cast<const float4*>(vsrc + r * K + q * 4);
            *reinterpret_cast<float4*>(Ks + r * PXK + q * 4) = kv;
            *reinterpret_cast<float4*>(Vs + r * PXK + q * 4) = vv;
        }
    }
    // ---- load side chunk [128][128] ----
    const float* sbase = side + ((size_t)b * C * T + t) * F + f0;
    #pragma unroll
    for (int idx = tid; idx < 128 * 32; idx += 256) {
        int r = idx >> 5, q = idx & 31;
        float4 v = *reinterpret_cast<const float4*>(sbase + (size_t)r * (T * F) + q * 4);
        *reinterpret_cast<float4*>(Xs + r * PXF + q * 4) = v;
    }
    __syncthreads();
    // ---- rmsnorm (axis C) ----
    if (tid < 128) {
        float s0 = 0, s1 = 0, s2 = 0, s3 = 0;
        for (int c = 0; c < 128; c += 4) {
            float a = Xs[c * PXF + tid], bb = Xs[(c + 1) * PXF + tid];
            float cc = Xs[(c + 2) * PXF + tid], dd = Xs[(c + 3) * PXF + tid];
            s0 += a * a; s1 += bb * bb; s2 += cc * cc; s3 += dd * dd;
        }
        rstd[tid] = rsqrtf((s0 + s1 + s2 + s3) * (1.0f / 128.0f) + 1e-6f);
    }
    __syncthreads();
    #pragma unroll
    for (int idx = tid; idx < 128 * 32; idx += 256) {
        int r = idx >> 5, q = idx & 31;
        float g = qn_gamma[r];
        float* d = Xs + r * PXF + q * 4;
        d[0] *= rstd[q * 4 + 0] * g; d[1] *= rstd[q * 4 + 1] * g;
        d[2] *= rstd[q * 4 + 2] * g; d[3] *= rstd[q * 4 + 3] * g;
    }

    // ---- GEMM1: qmlp_in (256 rows), gated -> m in Hs ----
    {
        ull acc[16][4] = {};
        gemm_core<16, 4, PXF>(qmlp_in_w, Xs, Wts, acc, tid);
        #pragma unroll
        for (int i = 0; i < 8; ++i) {
            int r = ty + 16 * i;
            float ba = qmlp_in_b[r], bg = qmlp_in_b[r + 128];
            #pragma unroll
            for (int jp = 0; jp < 4; ++jp) {
                float a0, a1, g0, g1;
                unpack2(acc[i][jp], a0, a1);
                unpack2(acc[i + 8][jp], g0, g1);
                a0 += ba; a1 += ba; g0 += bg; g1 += bg;
                int fl = 2 * (tx + 16 * jp);
                Hs[r * PXF + fl]     = a0 * silu_f(g0);
                Hs[r * PXF + fl + 1] = a1 * silu_f(g1);
            }
        }
    }
    // ---- GEMM2: qmlp_out -> query_h in Xs ----
    {
        ull acc[8][4] = {};
        gemm_core<8, 4, PXF>(qmlp_out_w, Hs, Wts, acc, tid);
        #pragma unroll
        for (int i = 0; i < 8; ++i) {
            int r = ty + 16 * i;
            float bias = qmlp_out_b[r];
            #pragma unroll
            for (int jp = 0; jp < 4; ++jp) {
                float lo, hi; unpack2(acc[i][jp], lo, hi);
                int fl = 2 * (tx + 16 * jp);
                Xs[r * PXF + fl] = lo + bias; Xs[r * PXF + fl + 1] = hi + bias;
            }
        }
    }
    // ---- GEMM3: q projection -> Hs ----
    {
        ull acc[8][4] = {};
        gemm_core<8, 4, PXF>(q_w, Xs, Wts, acc, tid);
        #pragma unroll
        for (int i = 0; i < 8; ++i) {
            int r = ty + 16 * i;
            float bias = q_b[r];
            #pragma unroll
            for (int jp = 0; jp < 4; ++jp) {
                float lo, hi; unpack2(acc[i][jp], lo, hi);
                int fl = 2 * (tx + 16 * jp);
                Hs[r * PXF + fl] = lo + bias; Hs[r * PXF + fl + 1] = hi + bias;
            }
        }
    }
    __syncthreads();   // q fully in Hs before scores

    // ---- scores [f][k] + softmax over k ----
    const int kg = tid & 7, fg = tid >> 3;    // k-octet lives in lane bits 0..2
    float wgt[4][8];
    {
        ull sacc[4][4] = {};
        #pragma unroll 2
        for (int c = 0; c < 128; ++c) {
            const float* qrow = Hs + c * PXF + fg * 4;
            const float* krow = Ks + c * PXK + kg * 8;
            ull kp[4];
            #pragma unroll
            for (int jp = 0; jp < 4; ++jp)
                kp[jp] = *reinterpret_cast<const ull*>(krow + 2 * jp);
            #pragma unroll
            for (int i = 0; i < 4; ++i) {
                float qv = qrow[i];
                ull qp = pack2(qv, qv);
                #pragma unroll
                for (int jp = 0; jp < 4; ++jp)
                    sacc[i][jp] = ffma2(qp, kp[jp], sacc[i][jp]);
            }
        }
        const float ssc = *score_scale, psc = *prior_scale;
        #pragma unroll
        for (int i = 0; i < 4; ++i) {
            float s[8];
            #pragma unroll
            for (int jp = 0; jp < 4; ++jp) unpack2(sacc[i][jp], s[2 * jp], s[2 * jp + 1]);
            int fglob = f0 + fg * 4 + i;
            #pragma unroll
            for (int j = 0; j < 8; ++j)
                s[j] = s[j] * ssc + basis[(kg * 8 + j) * F + fglob] * psc;
            float m = s[0];
            #pragma unroll
            for (int j = 1; j < 8; ++j) m = fmaxf(m, s[j]);
            #pragma unroll
            for (int d = 1; d < 8; d <<= 1) m = fmaxf(m, __shfl_xor_sync(0xffffffffu, m, d));
            float sum = 0;
            #pragma unroll
            for (int j = 0; j < 8; ++j) { float e = expf(s[j] - m); wgt[i][j] = e; sum += e; }
            #pragma unroll
            for (int d = 1; d < 8; d <<= 1) sum += __shfl_xor_sync(0xffffffffu, sum, d);
            float inv = 1.0f / sum;
            #pragma unroll
            for (int j = 0; j < 8; ++j) wgt[i][j] *= inv;
        }
    }
    __syncthreads();   // all reads of Ks done
    {   // store weights transposed into the dead Ks region: Ws[k][f], pitch PXF
        float* Ws = Ks;
        #pragma unroll
        for (int i = 0; i < 4; ++i) {
            int fl = fg * 4 + i;
            #pragma unroll
            for (int j = 0; j < 8; ++j) Ws[(kg * 8 + j) * PXF + fl] = wgt[i][j];
        }
    }
    __syncthreads();
    // ---- attended[c][f] = sum_k Ws[k][f] * Vs[c][k] -> Hs ----
    {
        ull acc[8][4] = {};
        const float* Ws = Ks;
        #pragma unroll 2
        for (int kk = 0; kk < 64; ++kk) {
            ull xp[4];
            #pragma unroll
            for (int jp = 0; jp < 4; ++jp)
                xp[jp] = *reinterpret_cast<const ull*>(Ws + kk * PXF + 2 * (tx + 16 * jp));
            #pragma unroll
            for (int i = 0; i < 8; ++i) {
                float v = Vs[(ty + 16 * i) * PXK + kk];
                ull vp = pack2(v, v);
                #pragma unroll
                for (int jp = 0; jp < 4; ++jp)
                    acc[i][jp] = ffma2(vp, xp[jp], acc[i][jp]);
            }
        }
        #pragma unroll
        for (int i = 0; i < 8; ++i) {
            int r = ty + 16 * i;
            #pragma unroll
            for (int jp = 0; jp < 4; ++jp) {
                float lo, hi; unpack2(acc[i][jp], lo, hi);
                int fl = 2 * (tx + 16 * jp);
                Hs[r * PXF + fl] = lo; Hs[r * PXF + fl + 1] = hi;
            }
        }
    }
    // ---- GEMM4: hidden = o_w @ attended + o_b + qss*query_h  -> Xs (in place) ----
    {
        ull acc[8][4] = {};
        gemm_core<8, 4, PXF>(o_w, Hs, Wts, acc, tid);
        const float qs = *query_skip_scale;
        #pragma unroll
        for (int i = 0; i < 8; ++i) {
            int r = ty + 16 * i;
            float bias = o_b[r];
            #pragma unroll
            for (int jp = 0; jp < 4; ++jp) {
                float lo, hi; unpack2(acc[i][jp], lo, hi);
                int fl = 2 * (tx + 16 * jp);
                lo += bias + qs * Xs[r * PXF + fl];
                hi += bias + qs * Xs[r * PXF + fl + 1];
                Xs[r * PXF + fl] = lo; Xs[r * PXF + fl + 1] = hi;
            }
        }
    }
    __syncthreads();
    // ---- FFN rmsnorm: Hs = rmsnorm(Xs)*ffn_gamma ----
    if (tid < 128) {
        float s0 = 0, s1 = 0, s2 = 0, s3 = 0;
        for (int c = 0; c < 128; c += 4) {
            float a = Xs[c * PXF + tid], bb = Xs[(c + 1) * PXF + tid];
            float cc = Xs[(c + 2) * PXF + tid], dd = Xs[(c + 3) * PXF + tid];
            s0 += a * a; s1 += bb * bb; s2 += cc * cc; s3 += dd * dd;
        }
        rstd[tid] = rsqrtf((s0 + s1 + s2 + s3) * (1.0f / 128.0f) + 1e-6f);
    }
    __syncthreads();
    #pragma unroll
    for (int idx = tid; idx < 128 * 32; idx += 256) {
        int r = idx >> 5, q = idx & 31;
        float g = ffn_gamma[r];
        const float* s = Xs + r * PXF + q * 4;
        float* d = Hs + r * PXF + q * 4;
        d[0] = s[0] * rstd[q * 4 + 0] * g; d[1] = s[1] * rstd[q * 4 + 1] * g;
        d[2] = s[2] * rstd[q * 4 + 2] * g; d[3] = s[3] * rstd[q * 4 + 3] * g;
    }
    // ---- GEMM5: ffn_in (256 rows), gated -> m2 back into Hs ----
    {
        ull acc[16][4] = {};
        gemm_core<16, 4, PXF>(ffn_in_w, Hs, Wts, acc, tid);
        __syncthreads();   // everyone done READING Hs before we overwrite it
        #pragma unroll
        for (int i = 0; i < 8; ++i) {
            int r = ty + 16 * i;
            float ba = ffn_in_b[r], bg = ffn_in_b[r + 128];
            #pragma unroll
            for (int jp = 0; jp < 4; ++jp) {
                float a0, a1, g0, g1;
                unpack2(acc[i][jp], a0, a1);
                unpack2(acc[i + 8][jp], g0, g1);
                a0 += ba; a1 += ba; g0 += bg; g1 += bg;
                int fl = 2 * (tx + 16 * jp);
                Hs[r * PXF + fl]     = a0 * silu_f(g0);
                Hs[r * PXF + fl + 1] = a1 * silu_f(g1);
            }
        }
    }
    // ---- GEMM6: out = ffn_out @ m2 + ffn_out_b + hidden -> global ----
    {
        ull acc[8][4] = {};
        gemm_core<8, 4, PXF>(ffn_out_w, Hs, Wts, acc, tid);
        float* obase = out + ((size_t)b * C * T + t) * F + f0;
        #pragma unroll
        for (int i = 0; i < 8; ++i) {
            int r = ty + 16 * i;
            float bias = ffn_out_b[r];
            #pragma unroll
            for (int jp = 0; jp < 4; ++jp) {
                float lo, hi; unpack2(acc[i][jp], lo, hi);
                int fl = 2 * (tx + 16 * jp);
                lo += bias + Xs[r * PXF + fl];
                hi += bias + Xs[r * PXF + fl + 1];
                float2 st = make_float2(lo, hi);
                *reinterpret_cast<float2*>(obase + (size_t)r * (T * F) + fl) = st;
            }
        }
    }
}

// ---------------------------------------------------------------------------
extern "C" void kernel_launch(void* const* d_in, const int* in_sizes, int n_in,
                              void* d_out, int out_size)
{
    const float* latent      = (const float*)d_in[0];
    const float* side        = (const float*)d_in[1];
    const float* basis       = (const float*)d_in[2];
    const float* lp_gamma    = (const float*)d_in[3];
    const float* lp_w        = (const float*)d_in[4];
    const float* lp_b        = (const float*)d_in[5];
    const float* qn_gamma    = (const float*)d_in[6];
    const float* qmlp_in_w   = (const float*)d_in[7];
    const float* qmlp_in_b   = (const float*)d_in[8];
    const float* qmlp_out_w  = (const float*)d_in[9];
    const float* qmlp_out_b  = (const float*)d_in[10];
    const float* q_w         = (const float*)d_in[11];
    const float* q_b         = (const float*)d_in[12];
    const float* k_w         = (const float*)d_in[13];
    const float* k_b         = (const float*)d_in[14];
    const float* v_w         = (const float*)d_in[15];
    const float* v_b         = (const float*)d_in[16];
    const float* o_w         = (const float*)d_in[17];
    const float* o_b         = (const float*)d_in[18];
    const float* ffn_gamma   = (const float*)d_in[19];
    const float* ffn_in_w    = (const float*)d_in[20];
    const float* ffn_in_b    = (const float*)d_in[21];
    const float* ffn_out_w   = (const float*)d_in[22];
    const float* ffn_out_b   = (const float*)d_in[23];
    const float* score_scale = (const float*)d_in[24];
    const float* prior_scale = (const float*)d_in[25];
    const float* qss         = (const float*)d_in[26];
    float* out = (float*)d_out;

    cudaFuncSetAttribute(latent_kernel, cudaFuncAttributeMaxDynamicSharedMemorySize, K1_SMEM_BYTES);
    cudaFuncSetAttribute(main_kernel,   cudaFuncAttributeMaxDynamicSharedMemorySize, K2_SMEM_BYTES);

    latent_kernel<<<B * T, 256, K1_SMEM_BYTES>>>(
        latent, lp_gamma, lp_w, lp_b, k_w, k_b, v_w, v_b);

    main_kernel<<<dim3(F / FC, T, B), 256, K2_SMEM_BYTES>>>(
        side, basis, qn_gamma,
        qmlp_in_w, qmlp_in_b, qmlp_out_w, qmlp_out_b,
        q_w, q_b, o_w, o_b,
        ffn_gamma, ffn_in_w, ffn_in_b, ffn_out_w, ffn_out_b,
        score_scale, prior_scale, qss, out);
}